// round 2
// baseline (speedup 1.0000x reference)
#include <cuda_runtime.h>

#define NN 10000
#define HID 16
#define LAB 7
#define KC 200
#define RPB 32
#define KSPLIT 2

__device__ int g_is64;
__device__ __align__(16) float g_deg_src[NN];
__device__ __align__(16) float g_deg_dst[NN];
__device__ __align__(16) float g_norm_src[NN];
__device__ __align__(16) float g_norm_dst[NN];
__device__ __align__(16) float g_h[NN * HID];   // raw features @ W1 (no norm)
__device__ __align__(16) float g_agg1[NN * HID];
__device__ __align__(16) float g_h2[NN * 8];    // (relu(...)·norm_src) @ W2, padded
__device__ __align__(16) float g_agg2[NN * 8];

// ---------- helpers ----------
__device__ __forceinline__ unsigned long long pack2(float x) {
    unsigned long long r;
    asm("mov.b64 %0, {%1, %1};" : "=l"(r) : "f"(x));
    return r;
}
__device__ __forceinline__ void fma2(unsigned long long& d, unsigned long long a,
                                     unsigned long long b) {
    asm("fma.rn.f32x2 %0, %1, %2, %0;" : "+l"(d) : "l"(a), "l"(b));
}
__device__ __forceinline__ float2 unpack2(unsigned long long v) {
    float2 u;
    asm("mov.b64 {%0, %1}, %2;" : "=f"(u.x), "=f"(u.y) : "l"(v));
    return u;
}
__device__ __forceinline__ void redg_v4(float* p, float4 v) {
    unsigned long long gp;
    asm("cvta.to.global.u64 %0, %1;" : "=l"(gp) : "l"(p));
    asm volatile("red.global.add.v4.f32 [%0], {%1, %2, %3, %4};"
                 ::"l"(gp), "f"(v.x), "f"(v.y), "f"(v.z), "f"(v.w) : "memory");
}
// read edge index, dtype decided at runtime; clamp so a wrong guess never traps
__device__ __forceinline__ int eidx(const void* p, int e, int is64) {
    int v = is64 ? (int)((const long long*)p)[e] : ((const int*)p)[e];
    return min(max(v, 0), NN - 1);
}

// ---------- K-1: detect index dtype ----------
__global__ void k_detect(const int* __restrict__ src) {
    if (threadIdx.x == 0 && blockIdx.x == 0) {
        int all_odd_zero = 1;
        for (int i = 1; i < 256; i += 2)
            if (src[i] != 0) { all_odd_zero = 0; break; }
        g_is64 = all_odd_zero;
    }
}

// ---------- K0: zero scratch ----------
__global__ void k_zero() {
    int i = blockIdx.x * blockDim.x + threadIdx.x;
    int stride = gridDim.x * blockDim.x;
    for (int t = i; t < NN; t += stride) { g_deg_src[t] = 0.f; g_deg_dst[t] = 0.f; }
    for (int t = i; t < NN * HID; t += stride) { g_h[t] = 0.f; g_agg1[t] = 0.f; }
    for (int t = i; t < NN * 8; t += stride) g_agg2[t] = 0.f;
}

// ---------- K1: degrees ----------
__global__ void k_deg(const void* __restrict__ src, const void* __restrict__ dst, int nE) {
    int e = blockIdx.x * blockDim.x + threadIdx.x;
    if (e >= nE) return;
    int is64 = g_is64;
    atomicAdd(&g_deg_src[eidx(src, e, is64)], 1.f);
    atomicAdd(&g_deg_dst[eidx(dst, e, is64)], 1.f);
}

// ---------- K2: norms ----------
__global__ void k_norm() {
    int n = blockIdx.x * blockDim.x + threadIdx.x;
    if (n >= NN) return;
    g_norm_src[n] = rsqrtf(fmaxf(g_deg_src[n], 1.f));
    g_norm_dst[n] = rsqrtf(fmaxf(g_deg_dst[n], 1.f));
}

// ---------- K3: big GEMM  g_h = features @ W1 ----------
__global__ void __launch_bounds__(256)
k_gemm1(const float* __restrict__ feat, const float* __restrict__ W1) {
    __shared__ float sF[RPB * (KC + 1)];   // 32 x 201
    __shared__ float sW[KC * HID];         // 200 x 16

    const int rowBase = blockIdx.x * RPB;
    const int ks = blockIdx.y;
    const int tid = threadIdx.x;
    const int w = tid >> 5;
    const int lane = tid & 31;

    unsigned long long acc[8];
#pragma unroll
    for (int i = 0; i < 8; i++) acc[i] = 0ull;

    const int chunks_per = (NN / KC) / KSPLIT;   // 25
    const int ch0 = ks * chunks_per;

    for (int ch = ch0; ch < ch0 + chunks_per; ch++) {
        const int c0 = ch * KC;
        for (int i = tid; i < RPB * KC; i += 256) {
            int r = i / KC, j = i - r * KC;
            int gr = rowBase + r;
            float v = (gr < NN) ? feat[(size_t)gr * NN + c0 + j] : 0.f;
            sF[r * (KC + 1) + j] = v;
        }
        {
            const float4* Wg = (const float4*)(W1 + (size_t)c0 * HID);
            float4* sW4 = (float4*)sW;
            for (int i = tid; i < KC * HID / 4; i += 256) sW4[i] = Wg[i];
        }
        __syncthreads();

#pragma unroll 5
        for (int jj = 0; jj < KC / 8; jj++) {
            const int j = jj * 8 + w;
            float f = sF[lane * (KC + 1) + j];
            unsigned long long f2 = pack2(f);
            const ulonglong2* wr = (const ulonglong2*)(sW + j * HID);
            ulonglong2 w0 = wr[0], w1 = wr[1], w2 = wr[2], w3 = wr[3];
            fma2(acc[0], w0.x, f2); fma2(acc[1], w0.y, f2);
            fma2(acc[2], w1.x, f2); fma2(acc[3], w1.y, f2);
            fma2(acc[4], w2.x, f2); fma2(acc[5], w2.y, f2);
            fma2(acc[6], w3.x, f2); fma2(acc[7], w3.y, f2);
        }
        __syncthreads();
    }

    // cross-warp reduction (reuse sF as scratch: 8*32*16 = 4096 <= 6432)
    float* red = sF;
#pragma unroll
    for (int i = 0; i < 8; i++) {
        float2 u = unpack2(acc[i]);
        red[(w * RPB + lane) * HID + 2 * i] = u.x;
        red[(w * RPB + lane) * HID + 2 * i + 1] = u.y;
    }
    __syncthreads();
    for (int v = tid; v < RPB * HID; v += 256) {
        int r = v >> 4, k = v & 15;
        int gr = rowBase + r;
        if (gr < NN) {
            float s = 0.f;
#pragma unroll
            for (int ww = 0; ww < 8; ww++) s += red[(ww * RPB + r) * HID + k];
            atomicAdd(&g_h[(size_t)gr * HID + k], s);
        }
    }
}

// ---------- K4: scatter layer 1 (norm_src folded into gather) ----------
__global__ void k_scatter1(const void* __restrict__ src, const void* __restrict__ dst,
                           int nE) {
    int e = blockIdx.x * blockDim.x + threadIdx.x;
    if (e >= nE) return;
    int is64 = g_is64;
    int s = eidx(src, e, is64), d = eidx(dst, e, is64);
    float f = g_norm_src[s];
    const float4* hp = (const float4*)(g_h + (size_t)s * HID);
    float* ap = g_agg1 + (size_t)d * HID;
#pragma unroll
    for (int q = 0; q < 4; q++) {
        float4 v = hp[q];
        v.x *= f; v.y *= f; v.z *= f; v.w *= f;
        redg_v4(ap + 4 * q, v);
    }
}

// ---------- K5: h1 = relu(agg1*norm_dst + b1); h2 = (h1*norm_src) @ W2 ----------
__global__ void k_layer2(const float* __restrict__ b1, const float* __restrict__ W2) {
    int n = blockIdx.x * blockDim.x + threadIdx.x;
    if (n >= NN) return;
    float nd = g_norm_dst[n], ns = g_norm_src[n];
    float h1[HID];
    const float4* ap = (const float4*)(g_agg1 + (size_t)n * HID);
#pragma unroll
    for (int q = 0; q < 4; q++) {
        float4 v = ap[q];
        h1[4 * q + 0] = fmaxf(fmaf(v.x, nd, __ldg(&b1[4 * q + 0])), 0.f);
        h1[4 * q + 1] = fmaxf(fmaf(v.y, nd, __ldg(&b1[4 * q + 1])), 0.f);
        h1[4 * q + 2] = fmaxf(fmaf(v.z, nd, __ldg(&b1[4 * q + 2])), 0.f);
        h1[4 * q + 3] = fmaxf(fmaf(v.w, nd, __ldg(&b1[4 * q + 3])), 0.f);
    }
    float o[LAB];
#pragma unroll
    for (int j = 0; j < LAB; j++) o[j] = 0.f;
#pragma unroll
    for (int k = 0; k < HID; k++) {
        float hv = h1[k];
#pragma unroll
        for (int j = 0; j < LAB; j++) o[j] = fmaf(hv, __ldg(&W2[k * LAB + j]), o[j]);
    }
#pragma unroll
    for (int j = 0; j < LAB; j++) g_h2[n * 8 + j] = ns * o[j];
    g_h2[n * 8 + 7] = 0.f;
}

// ---------- K6: scatter layer 2 ----------
__global__ void k_scatter2(const void* __restrict__ src, const void* __restrict__ dst,
                           int nE) {
    int e = blockIdx.x * blockDim.x + threadIdx.x;
    if (e >= nE) return;
    int is64 = g_is64;
    int s = eidx(src, e, is64), d = eidx(dst, e, is64);
    const float4* hp = (const float4*)(g_h2 + (size_t)s * 8);
    float4 v0 = hp[0], v1 = hp[1];   // v1.w == 0
    float* ap = g_agg2 + (size_t)d * 8;
    redg_v4(ap, v0);
    redg_v4(ap + 4, v1);
}

// ---------- K7: finalize out = agg2*norm_dst + b2 ----------
__global__ void k_final(const float* __restrict__ b2, float* __restrict__ out) {
    int i = blockIdx.x * blockDim.x + threadIdx.x;
    if (i >= NN * LAB) return;
    int n = i / LAB, j = i - n * LAB;
    out[i] = fmaf(g_agg2[n * 8 + j], g_norm_dst[n], __ldg(&b2[j]));
}

extern "C" void kernel_launch(void* const* d_in, const int* in_sizes, int n_in,
                              void* d_out, int out_size) {
    const float* feat = (const float*)d_in[0];
    const void* src = d_in[1];
    const void* dst = d_in[2];
    const float* W1 = (const float*)d_in[3];
    const float* b1 = (const float*)d_in[4];
    const float* W2 = (const float*)d_in[5];
    const float* b2 = (const float*)d_in[6];
    int nE = in_sizes[1];
    float* out = (float*)d_out;

    int eb = (nE + 255) / 256;

    k_detect<<<1, 32>>>((const int*)src);
    k_zero<<<256, 256>>>();
    k_deg<<<eb, 256>>>(src, dst, nE);
    k_norm<<<(NN + 255) / 256, 256>>>();
    dim3 g1((NN + RPB - 1) / RPB, KSPLIT);
    k_gemm1<<<g1, 256>>>(feat, W1);
    k_scatter1<<<eb, 256>>>(src, dst, nE);
    k_layer2<<<(NN + 255) / 256, 256>>>(b1, W2);
    k_scatter2<<<eb, 256>>>(src, dst, nE);
    k_final<<<(NN * LAB + 255) / 256, 256>>>(b2, out);
}